// round 9
// baseline (speedup 1.0000x reference)
#include <cuda_runtime.h>
#include <cuda_fp16.h>
#include <cstdint>

// ---------------------------------------------------------------------------
// Problem constants
// ---------------------------------------------------------------------------
#define HH    192
#define WW    192
#define NPIX  (HH*WW)          // 36864
#define NB    8                // 2 halves * batch 4
#define NHEAD 4

// ---------------------------------------------------------------------------
// Device scratch: only v round-trips.
// v layout: [n(8)][head(4)][pixel(36864)][hd(32)]
// ---------------------------------------------------------------------------
__device__ float g_v[8*4*NPIX*32];

// ---------------------------------------------------------------------------
// fp16 helpers (base-ISA mma.sync m16n8k16)
// ---------------------------------------------------------------------------
__device__ __forceinline__ uint32_t pkh2(float a, float b) {
    __half2 h = __floats2half2_rn(a, b);   // low half = a
    return *reinterpret_cast<uint32_t*>(&h);
}
__device__ __forceinline__ void mma_f16(float* c, const uint4& a, const uint2& b) {
    asm volatile(
        "mma.sync.aligned.m16n8k16.row.col.f32.f16.f16.f32 "
        "{%0,%1,%2,%3}, {%4,%5,%6,%7}, {%8,%9}, {%0,%1,%2,%3};"
        : "+f"(c[0]), "+f"(c[1]), "+f"(c[2]), "+f"(c[3])
        : "r"(a.x), "r"(a.y), "r"(a.z), "r"(a.w), "r"(b.x), "r"(b.y));
}

#define B_KSTRIDE 1026   // b32 per kstep block (16 ntiles x 64 + 2 pad)

// ---- fused-kernel smem map (b32/float units) --------------------------------
// [0 .. 4096)        A tile (64 pix x 128 k fp16, fragment-major + swizzle)
// [4096 .. 12304)    Bq (8 ksteps)
// [12304 .. 20512)   Bk (8 ksteps)
//   (region [0, 19584) overlaid by vs[4][136][36] during attention)
// [20512 .. 29728)   Ks: 4 heads x 64 pix x 36 (fp32)
// [29728 .. 38944)   Qs: 4 heads x 64 pix x 36 (fp32)
// [38944 .. 40096)   lepe weights [head][tap][hd]
// [40096 .. 40224)   lepe bias   [head][hd]
// [40224 .. 40288)   attn bias   [head][i*4+j]
#define SMF_BQ   4096
#define SMF_BK   12304
#define SMF_K    20512
#define SMF_Q    29728
#define SMF_LW   38944
#define SMF_LB   40096
#define SMF_BIAS 40224
#define SM_TOT_F (40288*4)     // 161152 B -> 1 CTA/SM

// ---- v-kernel smem map -------------------------------------------------------
// [0..4096) A   [4096..8200) B chunk   [8200..17416) Cs (4 x 64 x 36 fp32)
#define SMF_VB  4096
#define SMF_VC  8200
#define SM_TOT_V (17416*4)     // 69664 B -> 3 CTAs/SM

// ---------------------------------------------------------------------------
// B chunk staging (256 threads): weights [o(128)][k(128)] fp32 -> fp16 frag
// chunk c covers k = c*64 .. c*64+63 (4 ksteps of 16); Bc = destination base
// ---------------------------------------------------------------------------
__device__ __forceinline__ void stage_b_chunk(uint32_t* __restrict__ Bc,
                                              const float* __restrict__ w,
                                              int c, int tid)
{
    #pragma unroll
    for (int it = 0; it < 8; ++it) {
        int i   = it*256 + tid;      // 0..2047
        int o   = i >> 4;            // 0..127
        int k4l = i & 15;            // float4 index within 64-k chunk
        float4 v = __ldg((const float4*)(w + (size_t)o*128) + (c*16 + k4l));
        int ksl = k4l >> 2;          // kstep within chunk
        int kc  = (k4l & 3) * 4;     // col within k16
        int tg0 = (kc >> 1) & 3;     // 0 or 2
        int r   = kc >> 3;           // b-reg 0/1
        uint32_t base = (uint32_t)(ksl*B_KSTRIDE + (o>>3)*64 + ((o&7)*4 + tg0)*2 + r);
        Bc[base    ] = pkh2(v.x, v.y);
        Bc[base + 2] = pkh2(v.z, v.w);
    }
}

// ---------------------------------------------------------------------------
// MMA over one 4-kstep chunk; 8 warps: warp tile 32(M) x 32(N), M total 64
// ---------------------------------------------------------------------------
__device__ __forceinline__ void mma_chunk4(float acc[2][4][4],
                                           const uint32_t* __restrict__ As,
                                           const uint32_t* __restrict__ Bc,
                                           int ks0, int warp_m, int warp_n, int lane)
{
    #pragma unroll
    for (int l = 0; l < 4; ++l) {
        const int kg = ks0 + l;
        uint4 a[2];
        #pragma unroll
        for (int i = 0; i < 2; ++i) {
            uint32_t u = (uint32_t)((kg*4 + warp_m*2 + i)*32 + lane);
            u ^= (u >> 3) & 7;
            a[i] = *(const uint4*)(As + (size_t)u*4);
        }
        uint2 bf[4];
        #pragma unroll
        for (int j = 0; j < 4; ++j)
            bf[j] = *(const uint2*)(Bc + l*B_KSTRIDE + (warp_n*4 + j)*64 + lane*2);
        #pragma unroll
        for (int i = 0; i < 2; ++i)
            #pragma unroll
            for (int j = 0; j < 4; ++j)
                mma_f16(acc[i][j], a[i], bf[j]);
    }
}

__device__ __forceinline__ void acc_zero(float acc[2][4][4]) {
    #pragma unroll
    for (int i = 0; i < 2; ++i)
        #pragma unroll
        for (int j = 0; j < 4; ++j)
            #pragma unroll
            for (int e = 0; e < 4; ++e) acc[i][j][e] = 0.0f;
}

// acc -> Cs[head(4)][pix 64][36]
__device__ __forceinline__ void write_c_all(const float acc[2][4][4],
                                            float* __restrict__ Cs,
                                            int warp_m, int warp_n, int lane)
{
    const int g  = lane >> 2;
    const int tg = lane & 3;
    #pragma unroll
    for (int i = 0; i < 2; ++i) {
        int pl = warp_m*32 + i*16 + g;
        #pragma unroll
        for (int j = 0; j < 4; ++j) {
            int o0 = warp_n*32 + j*8 + 2*tg;
            int h0 = o0 & 3, h1 = (o0 + 1) & 3;
            int hd = o0 >> 2;
            Cs[(h0*64 + pl    )*36 + hd] = acc[i][j][0];
            Cs[(h1*64 + pl    )*36 + hd] = acc[i][j][1];
            Cs[(h0*64 + pl + 8)*36 + hd] = acc[i][j][2];
            Cs[(h1*64 + pl + 8)*36 + hd] = acc[i][j][3];
        }
    }
}

// ---------------------------------------------------------------------------
// A staging: 64 pixels x 128 k -> fp16 fragment-major + swizzle.
// ---------------------------------------------------------------------------
__device__ __forceinline__ void stage_a(uint32_t* __restrict__ As,
                                        const float* __restrict__ xb,
                                        int pix, int kh)
{
    const int mtile   = pix >> 4;
    const int g       = pix & 7;
    const int rowhalf = (pix >> 3) & 1;
    #pragma unroll 4
    for (int k2 = 0; k2 < 32; k2 += 2) {
        int k = kh*32 + k2;
        float f0 = __ldg(xb + (size_t)k2 * NPIX);
        float f1 = __ldg(xb + (size_t)(k2+1) * NPIX);
        int kstep = k >> 4;
        int kc    = k & 15;
        int colhalf = kc >> 3;
        int tg      = (kc >> 1) & 3;
        uint32_t u = (uint32_t)((kstep*4 + mtile)*32 + g*4 + tg);
        u ^= (u >> 3) & 7;
        As[u*4 + colhalf*2 + rowhalf] = pkh2(f0, f1);
    }
}

// ---------------------------------------------------------------------------
// Kernel 1: v = 1x1 conv (fp16 GEMM), M=64 linear blocks, 3 CTAs/SM
// ---------------------------------------------------------------------------
__global__ void __launch_bounds__(256, 3)
v_kernel(const float* __restrict__ x, const float* __restrict__ qkv_w)
{
    extern __shared__ __align__(16) float smf[];
    uint32_t* As = (uint32_t*)smf;
    uint32_t* Bc = (uint32_t*)(smf + SMF_VB);
    float*    Cs = smf + SMF_VC;

    const int tid    = threadIdx.x;
    const int lane   = tid & 31;
    const int wid    = tid >> 5;
    const int warp_m = wid >> 2;    // 0..1
    const int warp_n = wid & 3;     // 0..3
    const int n      = blockIdx.y;
    const int half   = n >> 2;
    const int b      = n & 3;
    const int p0     = blockIdx.x * 64;
    const size_t n4  = (size_t)n * 4;

    {
        const int pix = tid & 63;
        const int kh  = tid >> 6;
        const float* xb = x + ((size_t)(b*256 + half*128 + kh*32)) * NPIX + p0 + pix;
        stage_a(As, xb, pix, kh);
    }

    float acc[2][4][4];
    acc_zero(acc);
    #pragma unroll 1
    for (int c = 0; c < 2; ++c) {
        stage_b_chunk(Bc, qkv_w + 32768, c, tid);
        __syncthreads();
        mma_chunk4(acc, As, Bc, c*4, warp_m, warp_n, lane);
        __syncthreads();
    }

    write_c_all(acc, Cs, warp_m, warp_n, lane);
    __syncthreads();

    // drain: one (head,pixel) row per thread, 8 x STG.128 linear
    {
        int h   = tid >> 6;
        int pix = tid & 63;
        const float4* src = (const float4*)(Cs + (size_t)(h*64 + pix)*36);
        float4* d = (float4*)(g_v + ((n4 + h)*NPIX + (size_t)(p0 + pix))*32);
        #pragma unroll
        for (int c = 0; c < 8; ++c) d[c] = src[c];
    }
}

// ---------------------------------------------------------------------------
// Kernel 2: fused q,k GEMM + window attention + LePE, single attention phase.
// CTA = 2 rows x 32 cols, 256 threads, 1 CTA/SM.
// ---------------------------------------------------------------------------
__global__ void __launch_bounds__(256, 1)
qkv_attn_kernel(const float* __restrict__ x, const float* __restrict__ qkv_w,
                const float* __restrict__ lepe_w, const float* __restrict__ lepe_b,
                const float* __restrict__ bias_table, const int* __restrict__ rel_idx,
                float* __restrict__ out)
{
    extern __shared__ __align__(16) float smf[];
    uint32_t* As = (uint32_t*)smf;
    uint32_t* Bq = (uint32_t*)(smf + SMF_BQ);
    uint32_t* Bk = (uint32_t*)(smf + SMF_BK);
    float*    Ks = smf + SMF_K;
    float*    Qs = smf + SMF_Q;

    const int tid    = threadIdx.x;
    const int lane   = tid & 31;
    const int wid    = tid >> 5;
    const int warp_m = wid >> 2;    // 0..1
    const int warp_n = wid & 3;     // 0..3
    const int n      = blockIdx.z;
    const int half   = n >> 2;
    const int b      = n & 3;
    const int x0     = blockIdx.x * 32;
    const int y0     = blockIdx.y * 2;
    const size_t n4  = (size_t)n * 4;

    // stage per-head constants straight from raw inputs (tiny, L2-resident)
    for (int idx = tid; idx < 1152; idx += 256) {
        int head = idx / 288;
        int r    = idx % 288;
        int tap  = r >> 5;
        int hd   = r & 31;
        smf[SMF_LW + idx] = __ldg(&lepe_w[(hd*4 + head)*9 + tap]);
    }
    if (tid < 128) {
        smf[SMF_LB + tid] = __ldg(&lepe_b[(tid & 31)*4 + (tid >> 5)]);
    } else if (tid < 192) {
        int t2 = tid - 128;
        int head = t2 >> 4, ij = t2 & 15;
        smf[SMF_BIAS + t2] = __ldg(&bias_table[__ldg(&rel_idx[ij])*4 + head]);
    }

    // stage A: interior 2x32 tile
    {
        const int pix = tid & 63;                 // row*32 + col
        const int kh  = tid >> 6;
        const int gy  = y0 + (pix >> 5);
        const int gx  = x0 + (pix & 31);
        const float* xb = x + ((size_t)(b*256 + half*128 + kh*32)) * NPIX
                            + (size_t)gy*WW + gx;
        stage_a(As, xb, pix, kh);
    }
    // stage full Bk and Bq (8 ksteps each)
    stage_b_chunk(Bk,                 qkv_w + 16384, 0, tid);
    stage_b_chunk(Bk + 4*B_KSTRIDE,   qkv_w + 16384, 1, tid);
    stage_b_chunk(Bq,                 qkv_w,         0, tid);
    stage_b_chunk(Bq + 4*B_KSTRIDE,   qkv_w,         1, tid);
    __syncthreads();

    float acc[2][4][4];

    // ---- k pass: no intermediate syncs ----
    acc_zero(acc);
    mma_chunk4(acc, As, Bk,               0, warp_m, warp_n, lane);
    mma_chunk4(acc, As, Bk + 4*B_KSTRIDE, 4, warp_m, warp_n, lane);
    write_c_all(acc, Ks, warp_m, warp_n, lane);

    // ---- q pass ----
    acc_zero(acc);
    mma_chunk4(acc, As, Bq,               0, warp_m, warp_n, lane);
    mma_chunk4(acc, As, Bq + 4*B_KSTRIDE, 4, warp_m, warp_n, lane);
    write_c_all(acc, Qs, warp_m, warp_n, lane);
    __syncthreads();      // all warps done reading A/B -> vs overlay allowed

    // stage vs[head(4)][4x34 halo][36] from g_v (overlaying A/B region)
    for (int idx = tid; idx < 4*136*8; idx += 256) {
        int hh  = idx / 1088;
        int rem = idx - hh*1088;
        int pix = rem >> 3;
        int c8  = rem & 7;
        int py  = pix / 34;
        int px  = pix - py*34;
        int gy  = y0 - 1 + py;
        int gx  = x0 - 1 + px;
        float4 vv = make_float4(0.f, 0.f, 0.f, 0.f);
        if (gy >= 0 && gy < HH && gx >= 0 && gx < WW)
            vv = __ldg((const float4*)(g_v +
                    ((n4 + hh)*NPIX + (size_t)gy*WW + gx)*32) + c8);
        *(float4*)(smf + (size_t)(hh*136 + pix)*36 + c8*4) = vv;
    }
    __syncthreads();

    // attention + lepe: all 256 threads = 4 heads x 16 windows x 4 tokens
    {
        const float scale = 0.17677669529663687f;  // 1/sqrt(32)
        const int head = tid >> 6;
        const int t    = tid & 63;
        const int w    = t >> 2;
        const int i    = t & 3;
        const int sy   = i >> 1, sx = i & 1;
        const int lx   = 2*w + sx;
        const int gy   = y0 + sy, gx = x0 + lx;

        const float* qp = Qs + (size_t)(head*64 + sy*32 + lx)*36;
        float qr[32];
        #pragma unroll
        for (int c8 = 0; c8 < 8; ++c8) {
            float4 qv = *(const float4*)(qp + c8*4);
            qr[c8*4+0] = qv.x; qr[c8*4+1] = qv.y;
            qr[c8*4+2] = qv.z; qr[c8*4+3] = qv.w;
        }
        float lg[4];
        #pragma unroll
        for (int j = 0; j < 4; ++j) {
            const float* kp = Ks + (size_t)(head*64 + (j>>1)*32 + 2*w + (j&1))*36;
            float s = 0.f;
            #pragma unroll
            for (int c8 = 0; c8 < 8; ++c8) {
                float4 kv = *(const float4*)(kp + c8*4);
                s = fmaf(qr[c8*4+0], kv.x, s);
                s = fmaf(qr[c8*4+1], kv.y, s);
                s = fmaf(qr[c8*4+2], kv.z, s);
                s = fmaf(qr[c8*4+3], kv.w, s);
            }
            lg[j] = s*scale + smf[SMF_BIAS + head*16 + i*4 + j];
        }
        float m  = fmaxf(fmaxf(lg[0], lg[1]), fmaxf(lg[2], lg[3]));
        float a0 = expf(lg[0] - m);
        float a1 = expf(lg[1] - m);
        float a2 = expf(lg[2] - m);
        float a3 = expf(lg[3] - m);
        float inv = 1.0f / (a0 + a1 + a2 + a3);
        a0 *= inv; a1 *= inv; a2 *= inv; a3 *= inv;

        const float* vsb = smf + (size_t)head*136*36;
        const float* vj0 = vsb + (size_t)(1*34 + 1 + 2*w    )*36;
        const float* vj1 = vsb + (size_t)(1*34 + 1 + 2*w + 1)*36;
        const float* vj2 = vsb + (size_t)(2*34 + 1 + 2*w    )*36;
        const float* vj3 = vsb + (size_t)(2*34 + 1 + 2*w + 1)*36;
        const float* lwp = smf + SMF_LW + head*288;
        const float* lbp = smf + SMF_LB + head*32;

        const size_t ob = ((size_t)(b*256 + half*128 + head)) * NPIX
                        + (size_t)gy*WW + gx;
        #pragma unroll
        for (int c8 = 0; c8 < 8; ++c8) {
            float4 v0 = *(const float4*)(vj0 + c8*4);
            float4 v1 = *(const float4*)(vj1 + c8*4);
            float4 v2 = *(const float4*)(vj2 + c8*4);
            float4 v3 = *(const float4*)(vj3 + c8*4);

            float ox = a0*v0.x; ox = fmaf(a1, v1.x, ox); ox = fmaf(a2, v2.x, ox); ox = fmaf(a3, v3.x, ox);
            float oy = a0*v0.y; oy = fmaf(a1, v1.y, oy); oy = fmaf(a2, v2.y, oy); oy = fmaf(a3, v3.y, oy);
            float oz = a0*v0.z; oz = fmaf(a1, v1.z, oz); oz = fmaf(a2, v2.z, oz); oz = fmaf(a3, v3.z, oz);
            float ow = a0*v0.w; ow = fmaf(a1, v1.w, ow); ow = fmaf(a2, v2.w, ow); ow = fmaf(a3, v3.w, ow);

            #pragma unroll
            for (int tp = 0; tp < 9; ++tp) {
                int dy = tp / 3, dx = tp - dy*3;
                float4 vv = *(const float4*)(vsb +
                    (size_t)((sy + dy)*34 + lx + dx)*36 + c8*4);
                float4 wv = *(const float4*)(lwp + tp*32 + c8*4);
                ox = fmaf(wv.x, vv.x, ox);
                oy = fmaf(wv.y, vv.y, oy);
                oz = fmaf(wv.z, vv.z, oz);
                ow = fmaf(wv.w, vv.w, ow);
            }
            float4 bb = *(const float4*)(lbp + c8*4);
            ox += bb.x; oy += bb.y; oz += bb.z; ow += bb.w;

            out[ob + (size_t)(c8*4 + 0) * 4 * NPIX] = ox;
            out[ob + (size_t)(c8*4 + 1) * 4 * NPIX] = oy;
            out[ob + (size_t)(c8*4 + 2) * 4 * NPIX] = oz;
            out[ob + (size_t)(c8*4 + 3) * 4 * NPIX] = ow;
        }
    }
}

// ---------------------------------------------------------------------------
// Launcher
// ---------------------------------------------------------------------------
extern "C" void kernel_launch(void* const* d_in, const int* in_sizes, int n_in,
                              void* d_out, int out_size)
{
    const float* x          = (const float*)d_in[0];
    const float* qkv_w      = (const float*)d_in[1];
    const float* lepe_w     = (const float*)d_in[2];
    const float* lepe_b     = (const float*)d_in[3];
    const float* bias_table = (const float*)d_in[4];
    const int*   rel_idx    = (const int*)  d_in[5];
    float* out = (float*)d_out;

    cudaFuncSetAttribute(v_kernel, cudaFuncAttributeMaxDynamicSharedMemorySize, SM_TOT_V);
    cudaFuncSetAttribute(qkv_attn_kernel, cudaFuncAttributeMaxDynamicSharedMemorySize, SM_TOT_F);

    dim3 gv(NPIX/64, NB);            // 576 x 8
    v_kernel<<<gv, 256, SM_TOT_V>>>(x, qkv_w);

    dim3 gf(WW/32, HH/2, NB);        // 6 x 96 x 8
    qkv_attn_kernel<<<gf, 256, SM_TOT_F>>>(x, qkv_w, lepe_w, lepe_b,
                                           bias_table, rel_idx, out);
}

// round 10
// speedup vs baseline: 1.6884x; 1.6884x over previous
#include <cuda_runtime.h>
#include <cuda_fp16.h>
#include <cstdint>

// ---------------------------------------------------------------------------
// Problem constants
// ---------------------------------------------------------------------------
#define HH    192
#define WW    192
#define NPIX  (HH*WW)          // 36864
#define NB    8                // 2 halves * batch 4

// ---------------------------------------------------------------------------
// Device scratch: only v round-trips.
// ---------------------------------------------------------------------------
__device__ float g_v[8*4*NPIX*32];

// ---------------------------------------------------------------------------
// fp16 helpers (base-ISA mma.sync m16n8k16)
// ---------------------------------------------------------------------------
__device__ __forceinline__ uint32_t pkh2(float a, float b) {
    __half2 h = __floats2half2_rn(a, b);   // low half = a
    return *reinterpret_cast<uint32_t*>(&h);
}
__device__ __forceinline__ void mma_f16(float* c, const uint4& a, const uint2& b) {
    asm volatile(
        "mma.sync.aligned.m16n8k16.row.col.f32.f16.f16.f32 "
        "{%0,%1,%2,%3}, {%4,%5,%6,%7}, {%8,%9}, {%0,%1,%2,%3};"
        : "+f"(c[0]), "+f"(c[1]), "+f"(c[2]), "+f"(c[3])
        : "r"(a.x), "r"(a.y), "r"(a.z), "r"(a.w), "r"(b.x), "r"(b.y));
}

#define B_KSTRIDE 1026   // b32 per kstep block

// ---- fused-kernel smem map (float units) ------------------------------------
// [0 .. 4096)        A tile (64 pix x 128 k fp16 frags)
// [4096 .. 8200)     B chunk (4 ksteps)
// [8200 .. 9792)     pad (vs overlay uses [0, 9792) = 2*136*36 fp32)
// [9792 .. 14912)    Ks_h: 4 heads x 64 pix x 40 halves (fp16)
// [14912 .. 17472)   Qs_h: 2 heads x 64 pix x 40 halves (fp16)
// [17472 .. 18624)   lepe weights [head][tap][hd] fp32
// [18624 .. 18752)   lepe bias
// [18752 .. 18816)   attn bias
#define SMF_B    4096
#define SMF_KH   9792
#define SMF_QH   14912
#define SMF_LW   17472
#define SMF_LB   18624
#define SMF_BIAS 18752
#define SM_TOT_F (18816*4)     // 75264 B -> 3 CTAs/SM

// ---- v-kernel smem map -------------------------------------------------------
#define SMF_VB  4096
#define SMF_VC  8200
#define SM_TOT_V (17416*4)     // 69664 B -> 3 CTAs/SM

// ---------------------------------------------------------------------------
// B chunk staging (256 threads): weights [o(128)][k(128)] fp32 -> fp16 frag
// ---------------------------------------------------------------------------
__device__ __forceinline__ void stage_b_chunk(uint32_t* __restrict__ Bc,
                                              const float* __restrict__ w,
                                              int c, int tid)
{
    #pragma unroll
    for (int it = 0; it < 8; ++it) {
        int i   = it*256 + tid;      // 0..2047
        int o   = i >> 4;            // 0..127
        int k4l = i & 15;
        float4 v = __ldg((const float4*)(w + (size_t)o*128) + (c*16 + k4l));
        int ksl = k4l >> 2;
        int kc  = (k4l & 3) * 4;
        int tg0 = (kc >> 1) & 3;
        int r   = kc >> 3;
        uint32_t base = (uint32_t)(ksl*B_KSTRIDE + (o>>3)*64 + ((o&7)*4 + tg0)*2 + r);
        Bc[base    ] = pkh2(v.x, v.y);
        Bc[base + 2] = pkh2(v.z, v.w);
    }
}

// ---------------------------------------------------------------------------
// MMA over one 4-kstep chunk; 8 warps: warp tile 32(M) x 32(N), M total 64
// ---------------------------------------------------------------------------
__device__ __forceinline__ void mma_chunk4(float acc[2][4][4],
                                           const uint32_t* __restrict__ As,
                                           const uint32_t* __restrict__ Bc,
                                           int ks0, int warp_m, int warp_n, int lane)
{
    #pragma unroll
    for (int l = 0; l < 4; ++l) {
        const int kg = ks0 + l;
        uint4 a[2];
        #pragma unroll
        for (int i = 0; i < 2; ++i) {
            uint32_t u = (uint32_t)((kg*4 + warp_m*2 + i)*32 + lane);
            u ^= (u >> 3) & 7;
            a[i] = *(const uint4*)(As + (size_t)u*4);
        }
        uint2 bf[4];
        #pragma unroll
        for (int j = 0; j < 4; ++j)
            bf[j] = *(const uint2*)(Bc + l*B_KSTRIDE + (warp_n*4 + j)*64 + lane*2);
        #pragma unroll
        for (int i = 0; i < 2; ++i)
            #pragma unroll
            for (int j = 0; j < 4; ++j)
                mma_f16(acc[i][j], a[i], bf[j]);
    }
}

__device__ __forceinline__ void acc_zero(float acc[2][4][4]) {
    #pragma unroll
    for (int i = 0; i < 2; ++i)
        #pragma unroll
        for (int j = 0; j < 4; ++j)
            #pragma unroll
            for (int e = 0; e < 4; ++e) acc[i][j][e] = 0.0f;
}

// acc -> Cs fp32 [head(4)][pix 64][36]   (v_kernel epilogue)
__device__ __forceinline__ void write_c_all(const float acc[2][4][4],
                                            float* __restrict__ Cs,
                                            int warp_m, int warp_n, int lane)
{
    const int g  = lane >> 2;
    const int tg = lane & 3;
    #pragma unroll
    for (int i = 0; i < 2; ++i) {
        int pl = warp_m*32 + i*16 + g;
        #pragma unroll
        for (int j = 0; j < 4; ++j) {
            int o0 = warp_n*32 + j*8 + 2*tg;
            int h0 = o0 & 3, h1 = (o0 + 1) & 3;
            int hd = o0 >> 2;
            Cs[(h0*64 + pl    )*36 + hd] = acc[i][j][0];
            Cs[(h1*64 + pl    )*36 + hd] = acc[i][j][1];
            Cs[(h0*64 + pl + 8)*36 + hd] = acc[i][j][2];
            Cs[(h1*64 + pl + 8)*36 + hd] = acc[i][j][3];
        }
    }
}

// acc -> Ks_h fp16 [head(4)][pix 64][stride 40]
__device__ __forceinline__ void write_k_h(const float acc[2][4][4],
                                          __half* __restrict__ K,
                                          int warp_m, int warp_n, int lane)
{
    const int g  = lane >> 2;
    const int tg = lane & 3;
    #pragma unroll
    for (int i = 0; i < 2; ++i) {
        int pl = warp_m*32 + i*16 + g;
        #pragma unroll
        for (int j = 0; j < 4; ++j) {
            int o0 = warp_n*32 + j*8 + 2*tg;
            int h0 = o0 & 3, h1 = (o0 + 1) & 3;
            int hd = o0 >> 2;
            K[(h0*64 + pl    )*40 + hd] = __float2half_rn(acc[i][j][0]);
            K[(h1*64 + pl    )*40 + hd] = __float2half_rn(acc[i][j][1]);
            K[(h0*64 + pl + 8)*40 + hd] = __float2half_rn(acc[i][j][2]);
            K[(h1*64 + pl + 8)*40 + hd] = __float2half_rn(acc[i][j][3]);
        }
    }
}

// acc -> Qs_h fp16 [hh(2)][pix 64][40] for one head-pair
__device__ __forceinline__ void write_q_h(const float acc[2][4][4],
                                          __half* __restrict__ Q, int pair,
                                          int warp_m, int warp_n, int lane)
{
    const int g  = lane >> 2;
    const int tg = lane & 3;
    if ((tg & 1) != pair) return;
    #pragma unroll
    for (int i = 0; i < 2; ++i) {
        int pl = warp_m*32 + i*16 + g;
        #pragma unroll
        for (int j = 0; j < 4; ++j) {
            int o0 = warp_n*32 + j*8 + 2*tg;
            int hd = o0 >> 2;
            Q[(0*64 + pl    )*40 + hd] = __float2half_rn(acc[i][j][0]);
            Q[(1*64 + pl    )*40 + hd] = __float2half_rn(acc[i][j][1]);
            Q[(0*64 + pl + 8)*40 + hd] = __float2half_rn(acc[i][j][2]);
            Q[(1*64 + pl + 8)*40 + hd] = __float2half_rn(acc[i][j][3]);
        }
    }
}

// ---------------------------------------------------------------------------
// A staging: 64 pixels x 128 k -> fp16 fragment-major + swizzle.
// ---------------------------------------------------------------------------
__device__ __forceinline__ void stage_a(uint32_t* __restrict__ As,
                                        const float* __restrict__ xb,
                                        int pix, int kh)
{
    const int mtile   = pix >> 4;
    const int g       = pix & 7;
    const int rowhalf = (pix >> 3) & 1;
    #pragma unroll 4
    for (int k2 = 0; k2 < 32; k2 += 2) {
        int k = kh*32 + k2;
        float f0 = __ldg(xb + (size_t)k2 * NPIX);
        float f1 = __ldg(xb + (size_t)(k2+1) * NPIX);
        int kstep = k >> 4;
        int kc    = k & 15;
        int colhalf = kc >> 3;
        int tg      = (kc >> 1) & 3;
        uint32_t u = (uint32_t)((kstep*4 + mtile)*32 + g*4 + tg);
        u ^= (u >> 3) & 7;
        As[u*4 + colhalf*2 + rowhalf] = pkh2(f0, f1);
    }
}

// ---------------------------------------------------------------------------
// Kernel 1: v = 1x1 conv (fp16 GEMM), M=64 linear blocks, 3 CTAs/SM
// ---------------------------------------------------------------------------
__global__ void __launch_bounds__(256, 3)
v_kernel(const float* __restrict__ x, const float* __restrict__ qkv_w)
{
    extern __shared__ __align__(16) float smf[];
    uint32_t* As = (uint32_t*)smf;
    uint32_t* Bc = (uint32_t*)(smf + SMF_VB);
    float*    Cs = smf + SMF_VC;

    const int tid    = threadIdx.x;
    const int lane   = tid & 31;
    const int wid    = tid >> 5;
    const int warp_m = wid >> 2;
    const int warp_n = wid & 3;
    const int n      = blockIdx.y;
    const int half   = n >> 2;
    const int b      = n & 3;
    const int p0     = blockIdx.x * 64;
    const size_t n4  = (size_t)n * 4;

    {
        const int pix = tid & 63;
        const int kh  = tid >> 6;
        const float* xb = x + ((size_t)(b*256 + half*128 + kh*32)) * NPIX + p0 + pix;
        stage_a(As, xb, pix, kh);
    }

    float acc[2][4][4];
    acc_zero(acc);
    #pragma unroll 1
    for (int c = 0; c < 2; ++c) {
        stage_b_chunk(Bc, qkv_w + 32768, c, tid);
        __syncthreads();
        mma_chunk4(acc, As, Bc, c*4, warp_m, warp_n, lane);
        __syncthreads();
    }

    write_c_all(acc, Cs, warp_m, warp_n, lane);
    __syncthreads();

    {
        int h   = tid >> 6;
        int pix = tid & 63;
        const float4* src = (const float4*)(Cs + (size_t)(h*64 + pix)*36);
        float4* d = (float4*)(g_v + ((n4 + h)*NPIX + (size_t)(p0 + pix))*32);
        #pragma unroll
        for (int c = 0; c < 8; ++c) d[c] = src[c];
    }
}

// ---------------------------------------------------------------------------
// Kernel 2: fused q,k GEMM + window attention + LePE, pair-looped attention.
// CTA = 2 rows x 32 cols, 256 threads, 3 CTAs/SM.
// ---------------------------------------------------------------------------
__global__ void __launch_bounds__(256, 3)
qkv_attn_kernel(const float* __restrict__ x, const float* __restrict__ qkv_w,
                const float* __restrict__ lepe_w, const float* __restrict__ lepe_b,
                const float* __restrict__ bias_table, const int* __restrict__ rel_idx,
                float* __restrict__ out)
{
    extern __shared__ __align__(16) float smf[];
    uint32_t* As   = (uint32_t*)smf;
    uint32_t* Bc   = (uint32_t*)(smf + SMF_B);
    __half*   Ks_h = (__half*)(smf + SMF_KH);
    __half*   Qs_h = (__half*)(smf + SMF_QH);

    const int tid    = threadIdx.x;
    const int lane   = tid & 31;
    const int wid    = tid >> 5;
    const int warp_m = wid >> 2;
    const int warp_n = wid & 3;
    const int n      = blockIdx.z;
    const int half   = n >> 2;
    const int b      = n & 3;
    const int x0     = blockIdx.x * 32;
    const int y0     = blockIdx.y * 2;
    const size_t n4  = (size_t)n * 4;

    // stage per-head constants from raw inputs (tiny, L2-resident)
    for (int idx = tid; idx < 1152; idx += 256) {
        int head = idx / 288;
        int r    = idx % 288;
        int tap  = r >> 5;
        int hd   = r & 31;
        smf[SMF_LW + idx] = __ldg(&lepe_w[(hd*4 + head)*9 + tap]);
    }
    if (tid < 128) {
        smf[SMF_LB + tid] = __ldg(&lepe_b[(tid & 31)*4 + (tid >> 5)]);
    } else if (tid < 192) {
        int t2 = tid - 128;
        int head = t2 >> 4, ij = t2 & 15;
        smf[SMF_BIAS + t2] = __ldg(&bias_table[__ldg(&rel_idx[ij])*4 + head]);
    }

    // stage A: interior 2x32 tile
    {
        const int pix = tid & 63;
        const int kh  = tid >> 6;
        const int gy  = y0 + (pix >> 5);
        const int gx  = x0 + (pix & 31);
        const float* xb = x + ((size_t)(b*256 + half*128 + kh*32)) * NPIX
                            + (size_t)gy*WW + gx;
        stage_a(As, xb, pix, kh);
    }

    float acck[2][4][4];

    // ---- k pass (weights at +16384) ----
    acc_zero(acck);
    #pragma unroll 1
    for (int c = 0; c < 2; ++c) {
        stage_b_chunk(Bc, qkv_w + 16384, c, tid);
        __syncthreads();
        mma_chunk4(acck, As, Bc, c*4, warp_m, warp_n, lane);
        __syncthreads();
    }
    write_k_h(acck, Ks_h, warp_m, warp_n, lane);

    // ---- q pass (weights at +0) ----
    float acc[2][4][4];
    acc_zero(acc);
    #pragma unroll 1
    for (int c = 0; c < 2; ++c) {
        stage_b_chunk(Bc, qkv_w, c, tid);
        __syncthreads();
        mma_chunk4(acc, As, Bc, c*4, warp_m, warp_n, lane);
        __syncthreads();
    }
    // A and B regions now dead -> vs overlay allowed

    const float scale = 0.17677669529663687f;

    #pragma unroll 1
    for (int pair = 0; pair < 2; ++pair) {
        write_q_h(acc, Qs_h, pair, warp_m, warp_n, lane);

        // stage vs[hh(2)][4x34 halo][36] fp32 (overlaying A/B region)
        for (int idx = tid; idx < 2*136*8; idx += 256) {
            int hh  = idx / 1088;
            int rem = idx - hh*1088;
            int pix = rem >> 3;
            int c8  = rem & 7;
            int py  = pix / 34;
            int px  = pix - py*34;
            int gy  = y0 - 1 + py;
            int gx  = x0 - 1 + px;
            float4 vv = make_float4(0.f, 0.f, 0.f, 0.f);
            if (gy >= 0 && gy < HH && gx >= 0 && gx < WW)
                vv = __ldg((const float4*)(g_v +
                        ((n4 + pair*2 + hh)*NPIX + (size_t)gy*WW + gx)*32) + c8);
            *(float4*)(smf + (size_t)(hh*136 + pix)*36 + c8*4) = vv;
        }
        __syncthreads();

        // attention + lepe: 128 active threads = 2 heads x 16 windows x 4 tokens
        if (tid < 128) {
            const int hp   = tid >> 6;
            const int t    = tid & 63;
            const int w    = t >> 2;
            const int i    = t & 3;
            const int head = pair*2 + hp;
            const int sy   = i >> 1, sx = i & 1;
            const int lx   = 2*w + sx;
            const int gy   = y0 + sy, gx = x0 + lx;

            // q halves (packed)
            uint32_t qh[16];
            {
                const uint4* qp = (const uint4*)(Qs_h + (size_t)(hp*64 + sy*32 + lx)*40);
                #pragma unroll
                for (int r = 0; r < 4; ++r) *((uint4*)qh + r) = qp[r];
            }
            float lg[4];
            #pragma unroll
            for (int j = 0; j < 4; ++j) {
                const uint4* kp = (const uint4*)(Ks_h +
                    (size_t)(head*64 + (j>>1)*32 + 2*w + (j&1))*40);
                float s = 0.f;
                #pragma unroll
                for (int r = 0; r < 4; ++r) {
                    uint4 kk = kp[r];
                    const uint32_t* kw = (const uint32_t*)&kk;
                    #pragma unroll
                    for (int u = 0; u < 4; ++u) {
                        float2 kf = __half22float2(*(const __half2*)&kw[u]);
                        float2 qf = __half22float2(*(const __half2*)&qh[r*4 + u]);
                        s = fmaf(qf.x, kf.x, s);
                        s = fmaf(qf.y, kf.y, s);
                    }
                }
                lg[j] = s*scale + smf[SMF_BIAS + head*16 + i*4 + j];
            }
            float m  = fmaxf(fmaxf(lg[0], lg[1]), fmaxf(lg[2], lg[3]));
            float a0 = expf(lg[0] - m);
            float a1 = expf(lg[1] - m);
            float a2 = expf(lg[2] - m);
            float a3 = expf(lg[3] - m);
            float inv = 1.0f / (a0 + a1 + a2 + a3);
            a0 *= inv; a1 *= inv; a2 *= inv; a3 *= inv;

            const float* vsb = smf + (size_t)hp*136*36;
            const float* vj0 = vsb + (size_t)(1*34 + 1 + 2*w    )*36;
            const float* vj1 = vsb + (size_t)(1*34 + 1 + 2*w + 1)*36;
            const float* vj2 = vsb + (size_t)(2*34 + 1 + 2*w    )*36;
            const float* vj3 = vsb + (size_t)(2*34 + 1 + 2*w + 1)*36;
            const float* lwp = smf + SMF_LW + head*288;
            const float* lbp = smf + SMF_LB + head*32;

            const size_t ob = ((size_t)(b*256 + half*128 + head)) * NPIX
                            + (size_t)gy*WW + gx;
            #pragma unroll
            for (int c8 = 0; c8 < 8; ++c8) {
                float4 v0 = *(const float4*)(vj0 + c8*4);
                float4 v1 = *(const float4*)(vj1 + c8*4);
                float4 v2 = *(const float4*)(vj2 + c8*4);
                float4 v3 = *(const float4*)(vj3 + c8*4);

                float ox = a0*v0.x; ox = fmaf(a1, v1.x, ox); ox = fmaf(a2, v2.x, ox); ox = fmaf(a3, v3.x, ox);
                float oy = a0*v0.y; oy = fmaf(a1, v1.y, oy); oy = fmaf(a2, v2.y, oy); oy = fmaf(a3, v3.y, oy);
                float oz = a0*v0.z; oz = fmaf(a1, v1.z, oz); oz = fmaf(a2, v2.z, oz); oz = fmaf(a3, v3.z, oz);
                float ow = a0*v0.w; ow = fmaf(a1, v1.w, ow); ow = fmaf(a2, v2.w, ow); ow = fmaf(a3, v3.w, ow);

                #pragma unroll
                for (int tp = 0; tp < 9; ++tp) {
                    int dy = tp / 3, dx = tp - dy*3;
                    float4 vv = *(const float4*)(vsb +
                        (size_t)((sy + dy)*34 + lx + dx)*36 + c8*4);
                    float4 wv = *(const float4*)(lwp + tp*32 + c8*4);
                    ox = fmaf(wv.x, vv.x, ox);
                    oy = fmaf(wv.y, vv.y, oy);
                    oz = fmaf(wv.z, vv.z, oz);
                    ow = fmaf(wv.w, vv.w, ow);
                }
                float4 bb = *(const float4*)(lbp + c8*4);
                ox += bb.x; oy += bb.y; oz += bb.z; ow += bb.w;

                out[ob + (size_t)(c8*4 + 0) * 4 * NPIX] = ox;
                out[ob + (size_t)(c8*4 + 1) * 4 * NPIX] = oy;
                out[ob + (size_t)(c8*4 + 2) * 4 * NPIX] = oz;
                out[ob + (size_t)(c8*4 + 3) * 4 * NPIX] = ow;
            }
        }
        __syncthreads();   // pair reads done before Qs/vs rewritten
    }
}

// ---------------------------------------------------------------------------
// Launcher
// ---------------------------------------------------------------------------
extern "C" void kernel_launch(void* const* d_in, const int* in_sizes, int n_in,
                              void* d_out, int out_size)
{
    const float* x          = (const float*)d_in[0];
    const float* qkv_w      = (const float*)d_in[1];
    const float* lepe_w     = (const float*)d_in[2];
    const float* lepe_b     = (const float*)d_in[3];
    const float* bias_table = (const float*)d_in[4];
    const int*   rel_idx    = (const int*)  d_in[5];
    float* out = (float*)d_out;

    cudaFuncSetAttribute(v_kernel, cudaFuncAttributeMaxDynamicSharedMemorySize, SM_TOT_V);
    cudaFuncSetAttribute(qkv_attn_kernel, cudaFuncAttributeMaxDynamicSharedMemorySize, SM_TOT_F);

    dim3 gv(NPIX/64, NB);            // 576 x 8
    v_kernel<<<gv, 256, SM_TOT_V>>>(x, qkv_w);

    dim3 gf(WW/32, HH/2, NB);        // 6 x 96 x 8
    qkv_attn_kernel<<<gf, 256, SM_TOT_F>>>(x, qkv_w, lepe_w, lepe_b,
                                           bias_table, rel_idx, out);
}